// round 14
// baseline (speedup 1.0000x reference)
#include <cuda_runtime.h>
#include <cuda_fp16.h>
#include <math.h>
#include <cstdint>

#define BATCH 4
#define SEQ   2048
#define EMB   2048
#define HEAD  128
#define NSPLIT 4

// ------------------------- device scratch -------------------------
__device__ __half g_Xh [BATCH*SEQ*EMB];  // X single fp16
__device__ __half g_Bh [256*EMB];        // rows 0-127: WQ, 128-255: WK (single fp16)
__device__ __half g_Vh [HEAD*EMB];       // W_V as-is [h][k] (single fp16)
__device__ __half g_Qh [BATCH*SEQ*HEAD]; // Q single fp16, pre-scaled log2e/sqrt(128)
__device__ __half g_Khi[BATCH*SEQ*HEAD]; // K hi/lo (exact pair)
__device__ __half g_Klo[BATCH*SEQ*HEAD];
__device__ float g_O[NSPLIT][BATCH*SEQ*HEAD];
__device__ float g_m[NSPLIT][BATCH*SEQ];     // base-2 domain
__device__ float g_l[NSPLIT][BATCH*SEQ];

// ------------------------- helpers -------------------------
__device__ __forceinline__ void cp16s(unsigned sd, const void* gsrc) {
    asm volatile("cp.async.cg.shared.global [%0], [%1], 16;\n" :: "r"(sd), "l"(gsrc));
}
#define CP_COMMIT() asm volatile("cp.async.commit_group;\n" ::: "memory")
#define CP_WAIT(N)  asm volatile("cp.async.wait_group %0;\n" :: "n"(N) : "memory")

__device__ __forceinline__ unsigned smem_u32(const void* p) {
    return (unsigned)__cvta_generic_to_shared((void*)p);
}
__device__ __forceinline__ void ldsm_x4(unsigned addr, unsigned& r0, unsigned& r1,
                                        unsigned& r2, unsigned& r3) {
    asm volatile("ldmatrix.sync.aligned.m8n8.x4.shared.b16 {%0,%1,%2,%3}, [%4];"
                 : "=r"(r0), "=r"(r1), "=r"(r2), "=r"(r3) : "r"(addr));
}
__device__ __forceinline__ void mma_f16(float* c, const unsigned* a, const unsigned* b) {
    asm volatile(
        "mma.sync.aligned.m16n8k16.row.col.f32.f16.f16.f32 "
        "{%0,%1,%2,%3}, {%4,%5,%6,%7}, {%8,%9}, {%0,%1,%2,%3};"
        : "+f"(c[0]), "+f"(c[1]), "+f"(c[2]), "+f"(c[3])
        : "r"(a[0]), "r"(a[1]), "r"(a[2]), "r"(a[3]), "r"(b[0]), "r"(b[1]));
}
__device__ __forceinline__ unsigned cvt2_f16(float lo_val, float hi_val) {
    unsigned r;
    asm("cvt.rn.f16x2.f32 %0, %1, %2;" : "=r"(r) : "f"(hi_val), "f"(lo_val));
    return r;
}
__device__ __forceinline__ float f16_round(float x) {
    return __half2float(__float2half_rn(x));
}
__device__ __forceinline__ float ex2f(float x) {
    float y; asm("ex2.approx.f32 %0, %1;" : "=f"(y) : "f"(x)); return y;
}

// ---------------------------------------------------------------------------
// convert X -> single fp16
// ---------------------------------------------------------------------------
__global__ __launch_bounds__(256) void convert_x_kernel(const float* __restrict__ X)
{
    long i = ((long)blockIdx.x * 256 + threadIdx.x) * 4;
    float4 v = *(const float4*)(X + i);
    __half h[4] = {__float2half_rn(v.x), __float2half_rn(v.y),
                   __float2half_rn(v.z), __float2half_rn(v.w)};
    *(ushort4*)&g_Xh[i] = *(ushort4*)h;
}

// ---------------------------------------------------------------------------
// convert WQ/WK -> g_Bh, WV -> g_Vh (single fp16)
// ---------------------------------------------------------------------------
__global__ __launch_bounds__(256) void convert_wv_kernel(
    const float* __restrict__ WQ, const float* __restrict__ WK,
    const float* __restrict__ WV)
{
    long i = ((long)blockIdx.x * 256 + threadIdx.x) * 4;
    const float* src;
    __half* dst;
    long didx;
    if (i < 256L * EMB) {
        int r = (int)(i >> 11);
        long c = i & 2047;
        src = (r < 128) ? (WQ + (long)r * EMB + c) : (WK + (long)(r - 128) * EMB + c);
        dst = g_Bh; didx = i;
    } else {
        long j = i - 256L * EMB;
        src = WV + j;
        dst = g_Vh; didx = j;
    }
    float4 v = *(const float4*)src;
    __half h[4] = {__float2half_rn(v.x), __float2half_rn(v.y),
                   __float2half_rn(v.z), __float2half_rn(v.w)};
    *(ushort4*)&dst[didx] = *(ushort4*)h;
}

// ---------------------------------------------------------------------------
// mma.sync projection GEMM: Q/K(8192 x 128 each) = X @ B^T, single fp16.
// CTA 128x128 (grid 64 x 2), BK=64, double-buffered cp.async, 8 warps (4m x 2n)
// Epilogue: Q -> single fp16 (prescaled); K -> hi/lo fp16 pair.
// ---------------------------------------------------------------------------
#define PJ_ROWB  144                  // 64 fp16 = 128 B data + 16 B pad
#define PJ_ARR   (128*PJ_ROWB)        // 18432 B per tile array
#define PJ_BUF   (2*PJ_ARR)           // A, B = 36864 B
#define PJ_SMEM  (2*PJ_BUF)           // 73728 B

__global__ __launch_bounds__(256) void proj_mma_kernel()
{
    extern __shared__ unsigned char dsm8[];
    const unsigned sb = smem_u32(dsm8);

    const int tid = threadIdx.x;
    const int wid = tid >> 5;
    const int lane = tid & 31;
    const int wm = wid & 3;
    const int wn = wid >> 2;

    const int m0 = blockIdx.x * 128;
    const int nt = blockIdx.y;     // 0 -> Q, 1 -> K

    float acc[2][8][4];
#pragma unroll
    for (int m = 0; m < 2; m++)
#pragma unroll
        for (int n = 0; n < 8; n++)
#pragma unroll
            for (int q = 0; q < 4; q++) acc[m][n][q] = 0.f;

    auto load_tile = [&](int buf, int kt) {
        const unsigned base = sb + buf * PJ_BUF;
        const long kof = (long)kt * 64;
        for (int c = tid; c < 1024; c += 256) {
            int r = c >> 3, ch = c & 7;
            unsigned so = (unsigned)(r * PJ_ROWB + ch * 16);
            cp16s(base + so, g_Xh + (long)(m0 + r) * EMB + kof + ch * 8);
        }
        for (int c = tid; c < 1024; c += 256) {
            int r = c >> 3, ch = c & 7;
            unsigned so = (unsigned)(r * PJ_ROWB + ch * 16);
            cp16s(base + PJ_ARR + so, g_Bh + (long)(nt * 128 + r) * EMB + kof + ch * 8);
        }
        CP_COMMIT();
    };

    load_tile(0, 0);

    const int a_row_off = (lane & 7) + ((lane >> 3) & 1) * 8;
    const int a_kb_off  = (lane >> 4) * 8;
    const int b_n_off   = (lane & 7) + ((lane >> 3) >> 1) * 8;
    const int b_k_off   = ((lane >> 3) & 1) * 8;

    for (int kt = 0; kt < 32; kt++) {
        const int buf = kt & 1;
        __syncthreads();

        if (kt + 1 < 32) {
            load_tile(buf ^ 1, kt + 1);
            CP_WAIT(1);
        } else {
            CP_WAIT(0);
        }
        __syncthreads();

        const unsigned aA = sb + buf * PJ_BUF;
        const unsigned bB = aA + PJ_ARR;

#pragma unroll
        for (int kf = 0; kf < 4; kf++) {
            const int kb = kf * 16;
            unsigned aa[2][4];
#pragma unroll
            for (int m = 0; m < 2; m++) {
                unsigned row = (unsigned)(wm * 32 + m * 16 + a_row_off);
                unsigned off = row * PJ_ROWB + (unsigned)(kb + a_kb_off) * 2;
                ldsm_x4(aA + off, aa[m][0], aa[m][1], aa[m][2], aa[m][3]);
            }
            unsigned bb[8][2];
#pragma unroll
            for (int g = 0; g < 4; g++) {
                unsigned nrow = (unsigned)(wn * 64 + g * 16 + b_n_off);
                unsigned off = nrow * PJ_ROWB + (unsigned)(kb + b_k_off) * 2;
                ldsm_x4(bB + off, bb[g*2][0], bb[g*2][1], bb[g*2+1][0], bb[g*2+1][1]);
            }
#pragma unroll
            for (int m = 0; m < 2; m++)
#pragma unroll
                for (int n = 0; n < 8; n++) mma_f16(acc[m][n], aa[m], bb[n]);
        }
    }

    // ---- epilogue ----
    if (nt == 0) {
        // Q: single fp16, prescaled by log2e/sqrt(128)
        const float scl = 0.08838834764831845f * 1.4426950408889634f;
#pragma unroll
        for (int m = 0; m < 2; m++) {
            const int row = m0 + wm * 32 + m * 16 + (lane >> 2);
#pragma unroll
            for (int n = 0; n < 8; n++) {
                const int col = wn * 64 + n * 8 + (lane & 3) * 2;
                *(unsigned*)&g_Qh[(long)row * HEAD + col] =
                    cvt2_f16(acc[m][n][0] * scl, acc[m][n][1] * scl);
                *(unsigned*)&g_Qh[(long)(row + 8) * HEAD + col] =
                    cvt2_f16(acc[m][n][2] * scl, acc[m][n][3] * scl);
            }
        }
    } else {
        // K: exact fp16 hi/lo pair
#pragma unroll
        for (int m = 0; m < 2; m++) {
            const int row = m0 + wm * 32 + m * 16 + (lane >> 2);
#pragma unroll
            for (int n = 0; n < 8; n++) {
                const int col = wn * 64 + n * 8 + (lane & 3) * 2;
                float v0 = acc[m][n][0], v1 = acc[m][n][1];
                float v2 = acc[m][n][2], v3 = acc[m][n][3];
                *(unsigned*)&g_Khi[(long)row * HEAD + col] = cvt2_f16(v0, v1);
                *(unsigned*)&g_Klo[(long)row * HEAD + col] =
                    cvt2_f16(v0 - f16_round(v0), v1 - f16_round(v1));
                *(unsigned*)&g_Khi[(long)(row + 8) * HEAD + col] = cvt2_f16(v2, v3);
                *(unsigned*)&g_Klo[(long)(row + 8) * HEAD + col] =
                    cvt2_f16(v2 - f16_round(v2), v3 - f16_round(v3));
            }
        }
    }
}

// ---------------------------------------------------------------------------
// Tensor-core causal flash attention, fp16, split-K(4).
// S: 2-term (Q single x K hi/lo).  PV: single term.
// smem: Q 34816 | K bufs @34816 (2 x {H:17408,L:17408}) | V bufs @104448 (2 x 18432)
// ---------------------------------------------------------------------------
#define FL_QROWB 272
#define FL_KROWB 272
#define FL_VROWB 144
#define FL_QB 0
#define FL_KB 34816
#define FL_VB 104448
#define FL_SMEM 141312

__global__ __launch_bounds__(256) void flash_kernel()
{
    extern __shared__ unsigned char dsm8[];
    const unsigned sb = smem_u32(dsm8);

    const int tid = threadIdx.x;
    const int wm  = tid >> 5;
    const int lane = tid & 31;

    const int bid = blockIdx.x;
    const int qt = 15 - (bid >> 4);
    const int b  = (bid >> 2) & 3;
    const int sp = bid & 3;

    const int nkt   = 2 * (qt + 1);
    const int chunk = (nkt + NSPLIT - 1) / NSPLIT;
    const int kt_lo = sp * chunk;
    const int kt_hi = min(nkt, kt_lo + chunk);

    const long qrow0 = (long)b * SEQ + qt * 128;

    // Q tile (single fp16)
    for (int c = tid; c < 1024; c += 256) {
        int r = c >> 3, ch = c & 7;
        unsigned so = (unsigned)(r * FL_QROWB + ch * 16);
        // 128 rows x 128 fp16 = 128 rows x 16 chunks; 1024 iters cover 8 chunks/row... 
        // use 2048-chunk mapping instead:
        (void)so; (void)r; (void)ch;
        break;
    }
    for (int c = tid; c < 2048; c += 256) {
        int r = c >> 4, ch = c & 15;
        unsigned so = (unsigned)(r * FL_QROWB + ch * 16);
        cp16s(sb + FL_QB + so, g_Qh + (qrow0 + r) * HEAD + ch * 8);
    }

    auto load_kv = [&](int buf, int kt) {
        const unsigned kh = sb + FL_KB + buf * 34816;
        const unsigned vh = sb + FL_VB + buf * 18432;
        for (int c = tid; c < 1024; c += 256) {
            int r = c >> 4, ch = c & 15;
            unsigned so = (unsigned)(r * FL_KROWB + ch * 16);
            const long gix = ((long)b * SEQ + kt * 64 + r) * HEAD + ch * 8;
            cp16s(kh + so,         g_Khi + gix);
            cp16s(kh + 17408 + so, g_Klo + gix);
        }
        for (int c = tid; c < 1024; c += 256) {
            int r = c >> 3, ch = c & 7;
            unsigned so = (unsigned)(r * FL_VROWB + ch * 16);
            cp16s(vh + so, g_Vh + (long)r * EMB + kt * 64 + ch * 8);
        }
        CP_COMMIT();
    };

    if (kt_lo < kt_hi) load_kv(0, kt_lo);
    else CP_COMMIT();

    float o[16][4];
#pragma unroll
    for (int n = 0; n < 16; n++)
#pragma unroll
        for (int q = 0; q < 4; q++) o[n][q] = 0.f;
    float m0 = -1e30f, m1 = -1e30f;
    float l0 = 0.f, l1 = 0.f;

    const int a_row_off = (lane & 7) + ((lane >> 3) & 1) * 8;
    const int a_kb_off  = (lane >> 4) * 8;
    const int b_n_off   = (lane & 7) + ((lane >> 3) >> 1) * 8;
    const int b_k_off   = ((lane >> 3) & 1) * 8;

    for (int kt = kt_lo; kt < kt_hi; kt++) {
        const int buf = (kt - kt_lo) & 1;
        __syncthreads();

        if (kt + 1 < kt_hi) {
            load_kv(buf ^ 1, kt + 1);
            CP_WAIT(1);
        } else {
            CP_WAIT(0);
        }
        __syncthreads();

        const unsigned kH = sb + FL_KB + buf * 34816;
        const unsigned kL = kH + 17408;
        const unsigned vB = sb + FL_VB + buf * 18432;

        // ---- S = Q K^T, 2-term (Q single, K hi/lo) ----
        float s[8][4];
#pragma unroll
        for (int n = 0; n < 8; n++)
#pragma unroll
            for (int q = 0; q < 4; q++) s[n][q] = 0.f;

#pragma unroll
        for (int t = 0; t < 8; t++) {
            const int kb = t * 16;
            unsigned aoff = (unsigned)((wm * 16 + a_row_off) * FL_QROWB + (kb + a_kb_off) * 2);
            unsigned aq[4];
            ldsm_x4(sb + FL_QB + aoff, aq[0], aq[1], aq[2], aq[3]);
            unsigned bh[4][4], bl[4][4];
#pragma unroll
            for (int g = 0; g < 4; g++) {
                unsigned boff = (unsigned)((g * 16 + b_n_off) * FL_KROWB + (kb + b_k_off) * 2);
                ldsm_x4(kH + boff, bh[g][0], bh[g][1], bh[g][2], bh[g][3]);
                ldsm_x4(kL + boff, bl[g][0], bl[g][1], bl[g][2], bl[g][3]);
            }
#pragma unroll
            for (int g = 0; g < 4; g++) {
                mma_f16(s[2*g],   aq, bh[g]);
                mma_f16(s[2*g+1], aq, bh[g] + 2);
            }
#pragma unroll
            for (int g = 0; g < 4; g++) {
                mma_f16(s[2*g],   aq, bl[g]);
                mma_f16(s[2*g+1], aq, bl[g] + 2);
            }
        }

        // ---- causal mask ----
        const int qr0 = qt * 128 + wm * 16 + (lane >> 2);
        const int qr1 = qr0 + 8;
        if (kt * 64 + 63 > qt * 128 + wm * 16) {
#pragma unroll
            for (int n = 0; n < 8; n++) {
                int c0 = kt * 64 + n * 8 + (lane & 3) * 2;
                if (c0     > qr0) s[n][0] = -1e30f;
                if (c0 + 1 > qr0) s[n][1] = -1e30f;
                if (c0     > qr1) s[n][2] = -1e30f;
                if (c0 + 1 > qr1) s[n][3] = -1e30f;
            }
        }

        // ---- online softmax (base-2 domain) ----
        float mx0 = -1e30f, mx1 = -1e30f;
#pragma unroll
        for (int n = 0; n < 8; n++) {
            mx0 = fmaxf(mx0, fmaxf(s[n][0], s[n][1]));
            mx1 = fmaxf(mx1, fmaxf(s[n][2], s[n][3]));
        }
        mx0 = fmaxf(mx0, __shfl_xor_sync(0xffffffffu, mx0, 1));
        mx0 = fmaxf(mx0, __shfl_xor_sync(0xffffffffu, mx0, 2));
        mx1 = fmaxf(mx1, __shfl_xor_sync(0xffffffffu, mx1, 1));
        mx1 = fmaxf(mx1, __shfl_xor_sync(0xffffffffu, mx1, 2));

        const float mn0 = fmaxf(m0, mx0);
        const float mn1 = fmaxf(m1, mx1);
        const float fac0 = ex2f(m0 - mn0);
        const float fac1 = ex2f(m1 - mn1);

        unsigned pA[4][4];
        float ls0 = 0.f, ls1 = 0.f;
#pragma unroll
        for (int t = 0; t < 4; t++) {
            float p00 = ex2f(s[2*t][0] - mn0),   p01 = ex2f(s[2*t][1] - mn0);
            float p02 = ex2f(s[2*t][2] - mn1),   p03 = ex2f(s[2*t][3] - mn1);
            float p10 = ex2f(s[2*t+1][0] - mn0), p11 = ex2f(s[2*t+1][1] - mn0);
            float p12 = ex2f(s[2*t+1][2] - mn1), p13 = ex2f(s[2*t+1][3] - mn1);
            ls0 += (p00 + p01) + (p10 + p11);
            ls1 += (p02 + p03) + (p12 + p13);
            pA[t][0] = cvt2_f16(p00, p01);
            pA[t][1] = cvt2_f16(p02, p03);
            pA[t][2] = cvt2_f16(p10, p11);
            pA[t][3] = cvt2_f16(p12, p13);
        }
        l0 = l0 * fac0 + ls0;
        l1 = l1 * fac1 + ls1;
        m0 = mn0; m1 = mn1;
#pragma unroll
        for (int n = 0; n < 16; n++) {
            o[n][0] *= fac0; o[n][1] *= fac0;
            o[n][2] *= fac1; o[n][3] *= fac1;
        }

        // ---- O += P @ V : single-term fp16 ----
#pragma unroll
        for (int t = 0; t < 4; t++) {
#pragma unroll
            for (int h = 0; h < 2; h++) {
                unsigned vr[4][4];
#pragma unroll
                for (int g4 = 0; g4 < 4; g4++) {
                    const int g = h * 4 + g4;
                    unsigned boff = (unsigned)((g * 16 + b_n_off) * FL_VROWB + (t * 16 + b_k_off) * 2);
                    ldsm_x4(vB + boff, vr[g4][0], vr[g4][1], vr[g4][2], vr[g4][3]);
                }
#pragma unroll
                for (int g4 = 0; g4 < 4; g4++) {
                    const int g = h * 4 + g4;
                    mma_f16(o[2*g],   pA[t], vr[g4]);
                    mma_f16(o[2*g+1], pA[t], vr[g4] + 2);
                }
            }
        }
    }

    // ---- epilogue ----
    l0 += __shfl_xor_sync(0xffffffffu, l0, 1);
    l0 += __shfl_xor_sync(0xffffffffu, l0, 2);
    l1 += __shfl_xor_sync(0xffffffffu, l1, 1);
    l1 += __shfl_xor_sync(0xffffffffu, l1, 2);

    const int r0 = wm * 16 + (lane >> 2);
    float* __restrict__ Og = g_O[sp] + (qrow0) * HEAD;
#pragma unroll
    for (int n = 0; n < 16; n++) {
        const int col = n * 8 + (lane & 3) * 2;
        *(float2*)&Og[(long)r0 * HEAD + col]       = make_float2(o[n][0], o[n][1]);
        *(float2*)&Og[(long)(r0 + 8) * HEAD + col] = make_float2(o[n][2], o[n][3]);
    }
    if ((lane & 3) == 0) {
        const long rowg = (long)b * SEQ + qt * 128 + r0;
        g_m[sp][rowg] = m0;     g_l[sp][rowg] = l0;
        g_m[sp][rowg + 8] = m1; g_l[sp][rowg + 8] = l1;
    }
}

// ---------------------------------------------------------------------------
// Combine active splits only (base-2 weights), float4 vectorized.
// ---------------------------------------------------------------------------
__global__ __launch_bounds__(256) void combine_kernel(float* __restrict__ out)
{
    const int id = blockIdx.x * 256 + threadIdx.x;
    const long base = (long)id * 4;
    const int row = (int)(base >> 7);
    const int qt = (row & 2047) >> 7;
    const int nkt = 2 * (qt + 1);
    const int chunk = (nkt + NSPLIT - 1) / NSPLIT;
    const int ns = (nkt + chunk - 1) / chunk;   // active splits (2..4)

    float M = -1e30f;
    for (int s = 0; s < ns; s++) M = fmaxf(M, g_m[s][row]);

    float4 num = make_float4(0.f, 0.f, 0.f, 0.f);
    float den = 0.f;
    for (int s = 0; s < ns; s++) {
        float w = ex2f(g_m[s][row] - M);
        float4 ov = *(const float4*)&g_O[s][base];
        num.x += w * ov.x; num.y += w * ov.y;
        num.z += w * ov.z; num.w += w * ov.w;
        den += w * g_l[s][row];
    }
    float inv = 1.0f / den;
    *(float4*)&out[base] = make_float4(num.x*inv, num.y*inv, num.z*inv, num.w*inv);
}

// ---------------------------------------------------------------------------
extern "C" void kernel_launch(void* const* d_in, const int* in_sizes, int n_in,
                              void* d_out, int out_size)
{
    const float* X  = (const float*)d_in[0];
    const float* WQ = (const float*)d_in[1];
    const float* WK = (const float*)d_in[2];
    const float* WV = (const float*)d_in[3];
    float* out = (float*)d_out;

    cudaFuncSetAttribute(proj_mma_kernel,
                         cudaFuncAttributeMaxDynamicSharedMemorySize, PJ_SMEM);
    cudaFuncSetAttribute(flash_kernel,
                         cudaFuncAttributeMaxDynamicSharedMemorySize, FL_SMEM);

    convert_x_kernel<<<(BATCH*SEQ*EMB)/1024, 256>>>(X);                  // 0
    convert_wv_kernel<<<(384*EMB)/1024, 256>>>(WQ, WK, WV);              // 1
    proj_mma_kernel<<<dim3(64, 2), 256, PJ_SMEM>>>();                    // 2
    flash_kernel<<<BATCH * 16 * NSPLIT, 256, FL_SMEM>>>();               // 3
    combine_kernel<<<(BATCH*SEQ*HEAD/4)/256, 256>>>(out);                // 4
}

// round 15
// speedup vs baseline: 1.0381x; 1.0381x over previous
#include <cuda_runtime.h>
#include <cuda_fp16.h>
#include <math.h>
#include <cstdint>

#define BATCH 4
#define SEQ   2048
#define EMB   2048
#define HEAD  128
#define NSPLIT 4

// ------------------------- device scratch -------------------------
__device__ __half g_Xh [BATCH*SEQ*EMB];  // X single fp16
__device__ __half g_Bh [256*EMB];        // rows 0-127: WQ, 128-255: WK (single fp16)
__device__ __half g_Vh [HEAD*EMB];       // W_V as-is [h][k] (single fp16)
__device__ __half g_Qh [BATCH*SEQ*HEAD]; // Q single fp16, pre-scaled log2e/sqrt(128)
__device__ __half g_Kh [BATCH*SEQ*HEAD]; // K single fp16
__device__ float g_O[NSPLIT][BATCH*SEQ*HEAD];
__device__ float g_m[NSPLIT][BATCH*SEQ];     // base-2 domain
__device__ float g_l[NSPLIT][BATCH*SEQ];

// ------------------------- helpers -------------------------
__device__ __forceinline__ void cp16s(unsigned sd, const void* gsrc) {
    asm volatile("cp.async.cg.shared.global [%0], [%1], 16;\n" :: "r"(sd), "l"(gsrc));
}
#define CP_COMMIT() asm volatile("cp.async.commit_group;\n" ::: "memory")
#define CP_WAIT(N)  asm volatile("cp.async.wait_group %0;\n" :: "n"(N) : "memory")

__device__ __forceinline__ unsigned smem_u32(const void* p) {
    return (unsigned)__cvta_generic_to_shared((void*)p);
}
__device__ __forceinline__ void ldsm_x4(unsigned addr, unsigned& r0, unsigned& r1,
                                        unsigned& r2, unsigned& r3) {
    asm volatile("ldmatrix.sync.aligned.m8n8.x4.shared.b16 {%0,%1,%2,%3}, [%4];"
                 : "=r"(r0), "=r"(r1), "=r"(r2), "=r"(r3) : "r"(addr));
}
__device__ __forceinline__ void mma_f16(float* c, const unsigned* a, const unsigned* b) {
    asm volatile(
        "mma.sync.aligned.m16n8k16.row.col.f32.f16.f16.f32 "
        "{%0,%1,%2,%3}, {%4,%5,%6,%7}, {%8,%9}, {%0,%1,%2,%3};"
        : "+f"(c[0]), "+f"(c[1]), "+f"(c[2]), "+f"(c[3])
        : "r"(a[0]), "r"(a[1]), "r"(a[2]), "r"(a[3]), "r"(b[0]), "r"(b[1]));
}
__device__ __forceinline__ unsigned cvt2_f16(float lo_val, float hi_val) {
    unsigned r;
    asm("cvt.rn.f16x2.f32 %0, %1, %2;" : "=r"(r) : "f"(hi_val), "f"(lo_val));
    return r;
}
__device__ __forceinline__ float ex2f(float x) {
    float y; asm("ex2.approx.f32 %0, %1;" : "=f"(y) : "f"(x)); return y;
}

// ---------------------------------------------------------------------------
// convert X, WQ/WK, WV -> fp16 in ONE kernel
//   ids [0, XN)            -> g_Xh
//   ids [XN, XN+BN)        -> g_Bh
//   ids [XN+BN, XN+BN+VN)  -> g_Vh
// ---------------------------------------------------------------------------
#define XN ((long)BATCH*SEQ*EMB)
#define BN (256L*EMB)
#define VN ((long)HEAD*EMB)

__global__ __launch_bounds__(256) void convert_all_kernel(
    const float* __restrict__ X, const float* __restrict__ WQ,
    const float* __restrict__ WK, const float* __restrict__ WV)
{
    long i = ((long)blockIdx.x * 256 + threadIdx.x) * 4;
    const float* src;
    __half* dst;
    long didx;
    if (i < XN) {
        src = X + i; dst = g_Xh; didx = i;
    } else if (i < XN + BN) {
        long j = i - XN;
        int r = (int)(j >> 11);
        long c = j & 2047;
        src = (r < 128) ? (WQ + (long)r * EMB + c) : (WK + (long)(r - 128) * EMB + c);
        dst = g_Bh; didx = j;
    } else {
        long j = i - XN - BN;
        src = WV + j; dst = g_Vh; didx = j;
    }
    float4 v = *(const float4*)src;
    __half h[4] = {__float2half_rn(v.x), __float2half_rn(v.y),
                   __float2half_rn(v.z), __float2half_rn(v.w)};
    *(ushort4*)&dst[didx] = *(ushort4*)h;
}

// ---------------------------------------------------------------------------
// mma.sync projection GEMM: Q/K(8192 x 128 each) = X @ B^T, single fp16.
// CTA 128x128 (grid 64 x 2), BK=64, double-buffered cp.async, 8 warps (4m x 2n)
// ---------------------------------------------------------------------------
#define PJ_ROWB  144
#define PJ_ARR   (128*PJ_ROWB)
#define PJ_BUF   (2*PJ_ARR)
#define PJ_SMEM  (2*PJ_BUF)           // 73728 B

__global__ __launch_bounds__(256) void proj_mma_kernel()
{
    extern __shared__ unsigned char dsm8[];
    const unsigned sb = smem_u32(dsm8);

    const int tid = threadIdx.x;
    const int wid = tid >> 5;
    const int lane = tid & 31;
    const int wm = wid & 3;
    const int wn = wid >> 2;

    const int m0 = blockIdx.x * 128;
    const int nt = blockIdx.y;     // 0 -> Q, 1 -> K

    float acc[2][8][4];
#pragma unroll
    for (int m = 0; m < 2; m++)
#pragma unroll
        for (int n = 0; n < 8; n++)
#pragma unroll
            for (int q = 0; q < 4; q++) acc[m][n][q] = 0.f;

    auto load_tile = [&](int buf, int kt) {
        const unsigned base = sb + buf * PJ_BUF;
        const long kof = (long)kt * 64;
        for (int c = tid; c < 1024; c += 256) {
            int r = c >> 3, ch = c & 7;
            unsigned so = (unsigned)(r * PJ_ROWB + ch * 16);
            cp16s(base + so, g_Xh + (long)(m0 + r) * EMB + kof + ch * 8);
        }
        for (int c = tid; c < 1024; c += 256) {
            int r = c >> 3, ch = c & 7;
            unsigned so = (unsigned)(r * PJ_ROWB + ch * 16);
            cp16s(base + PJ_ARR + so, g_Bh + (long)(nt * 128 + r) * EMB + kof + ch * 8);
        }
        CP_COMMIT();
    };

    load_tile(0, 0);

    const int a_row_off = (lane & 7) + ((lane >> 3) & 1) * 8;
    const int a_kb_off  = (lane >> 4) * 8;
    const int b_n_off   = (lane & 7) + ((lane >> 3) >> 1) * 8;
    const int b_k_off   = ((lane >> 3) & 1) * 8;

    for (int kt = 0; kt < 32; kt++) {
        const int buf = kt & 1;
        __syncthreads();

        if (kt + 1 < 32) {
            load_tile(buf ^ 1, kt + 1);
            CP_WAIT(1);
        } else {
            CP_WAIT(0);
        }
        __syncthreads();

        const unsigned aA = sb + buf * PJ_BUF;
        const unsigned bB = aA + PJ_ARR;

#pragma unroll
        for (int kf = 0; kf < 4; kf++) {
            const int kb = kf * 16;
            unsigned aa[2][4];
#pragma unroll
            for (int m = 0; m < 2; m++) {
                unsigned row = (unsigned)(wm * 32 + m * 16 + a_row_off);
                unsigned off = row * PJ_ROWB + (unsigned)(kb + a_kb_off) * 2;
                ldsm_x4(aA + off, aa[m][0], aa[m][1], aa[m][2], aa[m][3]);
            }
            unsigned bb[8][2];
#pragma unroll
            for (int g = 0; g < 4; g++) {
                unsigned nrow = (unsigned)(wn * 64 + g * 16 + b_n_off);
                unsigned off = nrow * PJ_ROWB + (unsigned)(kb + b_k_off) * 2;
                ldsm_x4(bB + off, bb[g*2][0], bb[g*2][1], bb[g*2+1][0], bb[g*2+1][1]);
            }
#pragma unroll
            for (int m = 0; m < 2; m++)
#pragma unroll
                for (int n = 0; n < 8; n++) mma_f16(acc[m][n], aa[m], bb[n]);
        }
    }

    // ---- epilogue: single fp16 outputs (Q prescaled) ----
    __half* __restrict__ dst = nt ? g_Kh : g_Qh;
    const float scl = nt ? 1.0f : (0.08838834764831845f * 1.4426950408889634f);
#pragma unroll
    for (int m = 0; m < 2; m++) {
        const int row = m0 + wm * 32 + m * 16 + (lane >> 2);
#pragma unroll
        for (int n = 0; n < 8; n++) {
            const int col = wn * 64 + n * 8 + (lane & 3) * 2;
            *(unsigned*)&dst[(long)row * HEAD + col] =
                cvt2_f16(acc[m][n][0] * scl, acc[m][n][1] * scl);
            *(unsigned*)&dst[(long)(row + 8) * HEAD + col] =
                cvt2_f16(acc[m][n][2] * scl, acc[m][n][3] * scl);
        }
    }
}

// ---------------------------------------------------------------------------
// Tensor-core causal flash attention, fp16 single everywhere, split-K(4).
// smem: Q 34816 | K bufs @34816 (2 x 17408) | V bufs @69632 (2 x 18432)
// ---------------------------------------------------------------------------
#define FL_QROWB 272
#define FL_KROWB 272
#define FL_VROWB 144
#define FL_QB 0
#define FL_KB 34816
#define FL_VB 69632
#define FL_SMEM 106496

__global__ __launch_bounds__(256) void flash_kernel()
{
    extern __shared__ unsigned char dsm8[];
    const unsigned sb = smem_u32(dsm8);

    const int tid = threadIdx.x;
    const int wm  = tid >> 5;
    const int lane = tid & 31;

    const int bid = blockIdx.x;
    const int qt = 15 - (bid >> 4);
    const int b  = (bid >> 2) & 3;
    const int sp = bid & 3;

    const int nkt   = 2 * (qt + 1);
    const int chunk = (nkt + NSPLIT - 1) / NSPLIT;
    const int kt_lo = sp * chunk;
    const int kt_hi = min(nkt, kt_lo + chunk);

    const long qrow0 = (long)b * SEQ + qt * 128;

    // Q tile (single fp16)
    for (int c = tid; c < 2048; c += 256) {
        int r = c >> 4, ch = c & 15;
        unsigned so = (unsigned)(r * FL_QROWB + ch * 16);
        cp16s(sb + FL_QB + so, g_Qh + (qrow0 + r) * HEAD + ch * 8);
    }

    auto load_kv = [&](int buf, int kt) {
        const unsigned kh = sb + FL_KB + buf * 17408;
        const unsigned vh = sb + FL_VB + buf * 18432;
        for (int c = tid; c < 1024; c += 256) {
            int r = c >> 4, ch = c & 15;
            unsigned so = (unsigned)(r * FL_KROWB + ch * 16);
            cp16s(kh + so, g_Kh + ((long)b * SEQ + kt * 64 + r) * HEAD + ch * 8);
        }
        for (int c = tid; c < 1024; c += 256) {
            int r = c >> 3, ch = c & 7;
            unsigned so = (unsigned)(r * FL_VROWB + ch * 16);
            cp16s(vh + so, g_Vh + (long)r * EMB + kt * 64 + ch * 8);
        }
        CP_COMMIT();
    };

    if (kt_lo < kt_hi) load_kv(0, kt_lo);
    else CP_COMMIT();

    float o[16][4];
#pragma unroll
    for (int n = 0; n < 16; n++)
#pragma unroll
        for (int q = 0; q < 4; q++) o[n][q] = 0.f;
    float m0 = -1e30f, m1 = -1e30f;
    float l0 = 0.f, l1 = 0.f;

    const int a_row_off = (lane & 7) + ((lane >> 3) & 1) * 8;
    const int a_kb_off  = (lane >> 4) * 8;
    const int b_n_off   = (lane & 7) + ((lane >> 3) >> 1) * 8;
    const int b_k_off   = ((lane >> 3) & 1) * 8;

    for (int kt = kt_lo; kt < kt_hi; kt++) {
        const int buf = (kt - kt_lo) & 1;
        __syncthreads();

        if (kt + 1 < kt_hi) {
            load_kv(buf ^ 1, kt + 1);
            CP_WAIT(1);
        } else {
            CP_WAIT(0);
        }
        __syncthreads();

        const unsigned kB = sb + FL_KB + buf * 17408;
        const unsigned vB = sb + FL_VB + buf * 18432;

        // ---- S = Q K^T, single-term fp16 ----
        float s[8][4];
#pragma unroll
        for (int n = 0; n < 8; n++)
#pragma unroll
            for (int q = 0; q < 4; q++) s[n][q] = 0.f;

#pragma unroll
        for (int t = 0; t < 8; t++) {
            const int kb = t * 16;
            unsigned aoff = (unsigned)((wm * 16 + a_row_off) * FL_QROWB + (kb + a_kb_off) * 2);
            unsigned aq[4];
            ldsm_x4(sb + FL_QB + aoff, aq[0], aq[1], aq[2], aq[3]);
            unsigned bk[4][4];
#pragma unroll
            for (int g = 0; g < 4; g++) {
                unsigned boff = (unsigned)((g * 16 + b_n_off) * FL_KROWB + (kb + b_k_off) * 2);
                ldsm_x4(kB + boff, bk[g][0], bk[g][1], bk[g][2], bk[g][3]);
            }
#pragma unroll
            for (int g = 0; g < 4; g++) {
                mma_f16(s[2*g],   aq, bk[g]);
                mma_f16(s[2*g+1], aq, bk[g] + 2);
            }
        }

        // ---- causal mask ----
        const int qr0 = qt * 128 + wm * 16 + (lane >> 2);
        const int qr1 = qr0 + 8;
        if (kt * 64 + 63 > qt * 128 + wm * 16) {
#pragma unroll
            for (int n = 0; n < 8; n++) {
                int c0 = kt * 64 + n * 8 + (lane & 3) * 2;
                if (c0     > qr0) s[n][0] = -1e30f;
                if (c0 + 1 > qr0) s[n][1] = -1e30f;
                if (c0     > qr1) s[n][2] = -1e30f;
                if (c0 + 1 > qr1) s[n][3] = -1e30f;
            }
        }

        // ---- online softmax (base-2 domain) ----
        float mx0 = -1e30f, mx1 = -1e30f;
#pragma unroll
        for (int n = 0; n < 8; n++) {
            mx0 = fmaxf(mx0, fmaxf(s[n][0], s[n][1]));
            mx1 = fmaxf(mx1, fmaxf(s[n][2], s[n][3]));
        }
        mx0 = fmaxf(mx0, __shfl_xor_sync(0xffffffffu, mx0, 1));
        mx0 = fmaxf(mx0, __shfl_xor_sync(0xffffffffu, mx0, 2));
        mx1 = fmaxf(mx1, __shfl_xor_sync(0xffffffffu, mx1, 1));
        mx1 = fmaxf(mx1, __shfl_xor_sync(0xffffffffu, mx1, 2));

        const float mn0 = fmaxf(m0, mx0);
        const float mn1 = fmaxf(m1, mx1);
        const float fac0 = ex2f(m0 - mn0);
        const float fac1 = ex2f(m1 - mn1);

        unsigned pA[4][4];
        float ls0 = 0.f, ls1 = 0.f;
#pragma unroll
        for (int t = 0; t < 4; t++) {
            float p00 = ex2f(s[2*t][0] - mn0),   p01 = ex2f(s[2*t][1] - mn0);
            float p02 = ex2f(s[2*t][2] - mn1),   p03 = ex2f(s[2*t][3] - mn1);
            float p10 = ex2f(s[2*t+1][0] - mn0), p11 = ex2f(s[2*t+1][1] - mn0);
            float p12 = ex2f(s[2*t+1][2] - mn1), p13 = ex2f(s[2*t+1][3] - mn1);
            ls0 += (p00 + p01) + (p10 + p11);
            ls1 += (p02 + p03) + (p12 + p13);
            pA[t][0] = cvt2_f16(p00, p01);
            pA[t][1] = cvt2_f16(p02, p03);
            pA[t][2] = cvt2_f16(p10, p11);
            pA[t][3] = cvt2_f16(p12, p13);
        }
        l0 = l0 * fac0 + ls0;
        l1 = l1 * fac1 + ls1;
        m0 = mn0; m1 = mn1;
#pragma unroll
        for (int n = 0; n < 16; n++) {
            o[n][0] *= fac0; o[n][1] *= fac0;
            o[n][2] *= fac1; o[n][3] *= fac1;
        }

        // ---- O += P @ V : single-term fp16 ----
#pragma unroll
        for (int t = 0; t < 4; t++) {
#pragma unroll
            for (int h = 0; h < 2; h++) {
                unsigned vr[4][4];
#pragma unroll
                for (int g4 = 0; g4 < 4; g4++) {
                    const int g = h * 4 + g4;
                    unsigned boff = (unsigned)((g * 16 + b_n_off) * FL_VROWB + (t * 16 + b_k_off) * 2);
                    ldsm_x4(vB + boff, vr[g4][0], vr[g4][1], vr[g4][2], vr[g4][3]);
                }
#pragma unroll
                for (int g4 = 0; g4 < 4; g4++) {
                    const int g = h * 4 + g4;
                    mma_f16(o[2*g],   pA[t], vr[g4]);
                    mma_f16(o[2*g+1], pA[t], vr[g4] + 2);
                }
            }
        }
    }

    // ---- epilogue ----
    l0 += __shfl_xor_sync(0xffffffffu, l0, 1);
    l0 += __shfl_xor_sync(0xffffffffu, l0, 2);
    l1 += __shfl_xor_sync(0xffffffffu, l1, 1);
    l1 += __shfl_xor_sync(0xffffffffu, l1, 2);

    const int r0 = wm * 16 + (lane >> 2);
    float* __restrict__ Og = g_O[sp] + (qrow0) * HEAD;
#pragma unroll
    for (int n = 0; n < 16; n++) {
        const int col = n * 8 + (lane & 3) * 2;
        *(float2*)&Og[(long)r0 * HEAD + col]       = make_float2(o[n][0], o[n][1]);
        *(float2*)&Og[(long)(r0 + 8) * HEAD + col] = make_float2(o[n][2], o[n][3]);
    }
    if ((lane & 3) == 0) {
        const long rowg = (long)b * SEQ + qt * 128 + r0;
        g_m[sp][rowg] = m0;     g_l[sp][rowg] = l0;
        g_m[sp][rowg + 8] = m1; g_l[sp][rowg + 8] = l1;
    }
}

// ---------------------------------------------------------------------------
// Combine active splits only (base-2 weights), float4 vectorized.
// ---------------------------------------------------------------------------
__global__ __launch_bounds__(256) void combine_kernel(float* __restrict__ out)
{
    const int id = blockIdx.x * 256 + threadIdx.x;
    const long base = (long)id * 4;
    const int row = (int)(base >> 7);
    const int qt = (row & 2047) >> 7;
    const int nkt = 2 * (qt + 1);
    const int chunk = (nkt + NSPLIT - 1) / NSPLIT;
    const int ns = (nkt + chunk - 1) / chunk;

    float M = -1e30f;
    for (int s = 0; s < ns; s++) M = fmaxf(M, g_m[s][row]);

    float4 num = make_float4(0.f, 0.f, 0.f, 0.f);
    float den = 0.f;
    for (int s = 0; s < ns; s++) {
        float w = ex2f(g_m[s][row] - M);
        float4 ov = *(const float4*)&g_O[s][base];
        num.x += w * ov.x; num.y += w * ov.y;
        num.z += w * ov.z; num.w += w * ov.w;
        den += w * g_l[s][row];
    }
    float inv = 1.0f / den;
    *(float4*)&out[base] = make_float4(num.x*inv, num.y*inv, num.z*inv, num.w*inv);
}

// ---------------------------------------------------------------------------
extern "C" void kernel_launch(void* const* d_in, const int* in_sizes, int n_in,
                              void* d_out, int out_size)
{
    const float* X  = (const float*)d_in[0];
    const float* WQ = (const float*)d_in[1];
    const float* WK = (const float*)d_in[2];
    const float* WV = (const float*)d_in[3];
    float* out = (float*)d_out;

    cudaFuncSetAttribute(proj_mma_kernel,
                         cudaFuncAttributeMaxDynamicSharedMemorySize, PJ_SMEM);
    cudaFuncSetAttribute(flash_kernel,
                         cudaFuncAttributeMaxDynamicSharedMemorySize, FL_SMEM);

    convert_all_kernel<<<(int)((XN + BN + VN) / 1024), 256>>>(X, WQ, WK, WV); // 0
    proj_mma_kernel<<<dim3(64, 2), 256, PJ_SMEM>>>();                         // 1
    flash_kernel<<<BATCH * 16 * NSPLIT, 256, FL_SMEM>>>();                    // 2
    combine_kernel<<<(BATCH*SEQ*HEAD/4)/256, 256>>>(out);                     // 3
}

// round 16
// speedup vs baseline: 1.1558x; 1.1133x over previous
#include <cuda_runtime.h>
#include <cuda_fp16.h>
#include <math.h>
#include <cstdint>

#define BATCH 4
#define SEQ   2048
#define EMB   2048
#define HEAD  128
#define NSPLIT 4

// ------------------------- device scratch -------------------------
__device__ __half g_Xh [BATCH*SEQ*EMB];
__device__ __half g_Bh [256*EMB];        // rows 0-127: WQ, 128-255: WK
__device__ __half g_Vh [HEAD*EMB];       // W_V as-is [h][k]
__device__ __half g_Qh [BATCH*SEQ*HEAD]; // pre-scaled log2e/sqrt(128)
__device__ __half g_Kh [BATCH*SEQ*HEAD];
__device__ float g_O[NSPLIT][BATCH*SEQ*HEAD];
__device__ float g_m[NSPLIT][BATCH*SEQ];     // base-2 domain
__device__ float g_l[NSPLIT][BATCH*SEQ];

// ------------------------- helpers -------------------------
__device__ __forceinline__ void cp16s(unsigned sd, const void* gsrc) {
    asm volatile("cp.async.cg.shared.global [%0], [%1], 16;\n" :: "r"(sd), "l"(gsrc));
}
#define CP_COMMIT() asm volatile("cp.async.commit_group;\n" ::: "memory")
#define CP_WAIT(N)  asm volatile("cp.async.wait_group %0;\n" :: "n"(N) : "memory")

__device__ __forceinline__ unsigned smem_u32(const void* p) {
    return (unsigned)__cvta_generic_to_shared((void*)p);
}
__device__ __forceinline__ void ldsm_x4(unsigned addr, unsigned& r0, unsigned& r1,
                                        unsigned& r2, unsigned& r3) {
    asm volatile("ldmatrix.sync.aligned.m8n8.x4.shared.b16 {%0,%1,%2,%3}, [%4];"
                 : "=r"(r0), "=r"(r1), "=r"(r2), "=r"(r3) : "r"(addr));
}
__device__ __forceinline__ void mma_f16(float* c, const unsigned* a, const unsigned* b) {
    asm volatile(
        "mma.sync.aligned.m16n8k16.row.col.f32.f16.f16.f32 "
        "{%0,%1,%2,%3}, {%4,%5,%6,%7}, {%8,%9}, {%0,%1,%2,%3};"
        : "+f"(c[0]), "+f"(c[1]), "+f"(c[2]), "+f"(c[3])
        : "r"(a[0]), "r"(a[1]), "r"(a[2]), "r"(a[3]), "r"(b[0]), "r"(b[1]));
}
__device__ __forceinline__ unsigned cvt2_f16(float lo_val, float hi_val) {
    unsigned r;
    asm("cvt.rn.f16x2.f32 %0, %1, %2;" : "=r"(r) : "f"(hi_val), "f"(lo_val));
    return r;
}
__device__ __forceinline__ float ex2f(float x) {
    float y; asm("ex2.approx.f32 %0, %1;" : "=f"(y) : "f"(x)); return y;
}

// ---------------------------------------------------------------------------
// convert X, WQ/WK, WV -> fp16 in ONE kernel
// ---------------------------------------------------------------------------
#define XN ((long)BATCH*SEQ*EMB)
#define BN (256L*EMB)
#define VN ((long)HEAD*EMB)

__global__ __launch_bounds__(256) void convert_all_kernel(
    const float* __restrict__ X, const float* __restrict__ WQ,
    const float* __restrict__ WK, const float* __restrict__ WV)
{
    long i = ((long)blockIdx.x * 256 + threadIdx.x) * 4;
    const float* src;
    __half* dst;
    long didx;
    if (i < XN) {
        src = X + i; dst = g_Xh; didx = i;
    } else if (i < XN + BN) {
        long j = i - XN;
        int r = (int)(j >> 11);
        long c = j & 2047;
        src = (r < 128) ? (WQ + (long)r * EMB + c) : (WK + (long)(r - 128) * EMB + c);
        dst = g_Bh; didx = j;
    } else {
        long j = i - XN - BN;
        src = WV + j; dst = g_Vh; didx = j;
    }
    float4 v = *(const float4*)src;
    __half h[4] = {__float2half_rn(v.x), __float2half_rn(v.y),
                   __float2half_rn(v.z), __float2half_rn(v.w)};
    *(ushort4*)&dst[didx] = *(ushort4*)h;
}

// ---------------------------------------------------------------------------
// mma.sync projection GEMM: Q/K(8192 x 128 each) = X @ B^T, single fp16.
// ---------------------------------------------------------------------------
#define PJ_ROWB  144
#define PJ_ARR   (128*PJ_ROWB)
#define PJ_BUF   (2*PJ_ARR)
#define PJ_SMEM  (2*PJ_BUF)           // 73728 B

__global__ __launch_bounds__(256) void proj_mma_kernel()
{
    extern __shared__ unsigned char dsm8[];
    const unsigned sb = smem_u32(dsm8);

    const int tid = threadIdx.x;
    const int wid = tid >> 5;
    const int lane = tid & 31;
    const int wm = wid & 3;
    const int wn = wid >> 2;

    const int m0 = blockIdx.x * 128;
    const int nt = blockIdx.y;

    float acc[2][8][4];
#pragma unroll
    for (int m = 0; m < 2; m++)
#pragma unroll
        for (int n = 0; n < 8; n++)
#pragma unroll
            for (int q = 0; q < 4; q++) acc[m][n][q] = 0.f;

    auto load_tile = [&](int buf, int kt) {
        const unsigned base = sb + buf * PJ_BUF;
        const long kof = (long)kt * 64;
        for (int c = tid; c < 1024; c += 256) {
            int r = c >> 3, ch = c & 7;
            unsigned so = (unsigned)(r * PJ_ROWB + ch * 16);
            cp16s(base + so, g_Xh + (long)(m0 + r) * EMB + kof + ch * 8);
        }
        for (int c = tid; c < 1024; c += 256) {
            int r = c >> 3, ch = c & 7;
            unsigned so = (unsigned)(r * PJ_ROWB + ch * 16);
            cp16s(base + PJ_ARR + so, g_Bh + (long)(nt * 128 + r) * EMB + kof + ch * 8);
        }
        CP_COMMIT();
    };

    load_tile(0, 0);

    const int a_row_off = (lane & 7) + ((lane >> 3) & 1) * 8;
    const int a_kb_off  = (lane >> 4) * 8;
    const int b_n_off   = (lane & 7) + ((lane >> 3) >> 1) * 8;
    const int b_k_off   = ((lane >> 3) & 1) * 8;

    for (int kt = 0; kt < 32; kt++) {
        const int buf = kt & 1;
        __syncthreads();

        if (kt + 1 < 32) {
            load_tile(buf ^ 1, kt + 1);
            CP_WAIT(1);
        } else {
            CP_WAIT(0);
        }
        __syncthreads();

        const unsigned aA = sb + buf * PJ_BUF;
        const unsigned bB = aA + PJ_ARR;

#pragma unroll
        for (int kf = 0; kf < 4; kf++) {
            const int kb = kf * 16;
            unsigned aa[2][4];
#pragma unroll
            for (int m = 0; m < 2; m++) {
                unsigned row = (unsigned)(wm * 32 + m * 16 + a_row_off);
                unsigned off = row * PJ_ROWB + (unsigned)(kb + a_kb_off) * 2;
                ldsm_x4(aA + off, aa[m][0], aa[m][1], aa[m][2], aa[m][3]);
            }
            unsigned bb[8][2];
#pragma unroll
            for (int g = 0; g < 4; g++) {
                unsigned nrow = (unsigned)(wn * 64 + g * 16 + b_n_off);
                unsigned off = nrow * PJ_ROWB + (unsigned)(kb + b_k_off) * 2;
                ldsm_x4(bB + off, bb[g*2][0], bb[g*2][1], bb[g*2+1][0], bb[g*2+1][1]);
            }
#pragma unroll
            for (int m = 0; m < 2; m++)
#pragma unroll
                for (int n = 0; n < 8; n++) mma_f16(acc[m][n], aa[m], bb[n]);
        }
    }

    __half* __restrict__ dst = nt ? g_Kh : g_Qh;
    const float scl = nt ? 1.0f : (0.08838834764831845f * 1.4426950408889634f);
#pragma unroll
    for (int m = 0; m < 2; m++) {
        const int row = m0 + wm * 32 + m * 16 + (lane >> 2);
#pragma unroll
        for (int n = 0; n < 8; n++) {
            const int col = wn * 64 + n * 8 + (lane & 3) * 2;
            *(unsigned*)&dst[(long)row * HEAD + col] =
                cvt2_f16(acc[m][n][0] * scl, acc[m][n][1] * scl);
            *(unsigned*)&dst[(long)(row + 8) * HEAD + col] =
                cvt2_f16(acc[m][n][2] * scl, acc[m][n][3] * scl);
        }
    }
}

// ---------------------------------------------------------------------------
// Tensor-core causal flash attention, fp16 single, split-K(4), 128-wide k-tiles.
// smem: Q 34816 | K bufs @34816 (2 x 34816) | V bufs @104448 (2 x 34816)
// ---------------------------------------------------------------------------
#define FL_QROWB 272
#define FL_KROWB 272
#define FL_VROWB 272
#define FL_QB 0
#define FL_KB 34816
#define FL_VB 104448
#define FL_SMEM 174080

__global__ __launch_bounds__(256) void flash_kernel()
{
    extern __shared__ unsigned char dsm8[];
    const unsigned sb = smem_u32(dsm8);

    const int tid = threadIdx.x;
    const int wm  = tid >> 5;
    const int lane = tid & 31;

    const int bid = blockIdx.x;
    const int qt = 15 - (bid >> 4);
    const int b  = (bid >> 2) & 3;
    const int sp = bid & 3;

    const int nkt   = qt + 1;                      // 128-wide tiles
    const int chunk = (nkt + NSPLIT - 1) / NSPLIT;
    const int kt_lo = sp * chunk;
    const int kt_hi = min(nkt, kt_lo + chunk);

    const long qrow0 = (long)b * SEQ + qt * 128;

    // Q tile
    for (int c = tid; c < 2048; c += 256) {
        int r = c >> 4, ch = c & 15;
        unsigned so = (unsigned)(r * FL_QROWB + ch * 16);
        cp16s(sb + FL_QB + so, g_Qh + (qrow0 + r) * HEAD + ch * 8);
    }

    auto load_kv = [&](int buf, int kt) {
        const unsigned kh = sb + FL_KB + buf * 34816;
        const unsigned vh = sb + FL_VB + buf * 34816;
        // K: 128 rows x 128 fp16
        for (int c = tid; c < 2048; c += 256) {
            int r = c >> 4, ch = c & 15;
            unsigned so = (unsigned)(r * FL_KROWB + ch * 16);
            cp16s(kh + so, g_Kh + ((long)b * SEQ + kt * 128 + r) * HEAD + ch * 8);
        }
        // V: 128 h-rows x 128 k-cols
        for (int c = tid; c < 2048; c += 256) {
            int r = c >> 4, ch = c & 15;
            unsigned so = (unsigned)(r * FL_VROWB + ch * 16);
            cp16s(vh + so, g_Vh + (long)r * EMB + kt * 128 + ch * 8);
        }
        CP_COMMIT();
    };

    if (kt_lo < kt_hi) load_kv(0, kt_lo);
    else CP_COMMIT();

    float o[16][4];
#pragma unroll
    for (int n = 0; n < 16; n++)
#pragma unroll
        for (int q = 0; q < 4; q++) o[n][q] = 0.f;
    float m0 = -1e30f, m1 = -1e30f;
    float l0 = 0.f, l1 = 0.f;

    const int a_row_off = (lane & 7) + ((lane >> 3) & 1) * 8;
    const int a_kb_off  = (lane >> 4) * 8;
    const int b_n_off   = (lane & 7) + ((lane >> 3) >> 1) * 8;
    const int b_k_off   = ((lane >> 3) & 1) * 8;

    for (int kt = kt_lo; kt < kt_hi; kt++) {
        const int buf = (kt - kt_lo) & 1;
        __syncthreads();

        if (kt + 1 < kt_hi) {
            load_kv(buf ^ 1, kt + 1);
            CP_WAIT(1);
        } else {
            CP_WAIT(0);
        }
        __syncthreads();

        const unsigned kB = sb + FL_KB + buf * 34816;
        const unsigned vB = sb + FL_VB + buf * 34816;

        // ---- S = Q K^T : 128 q-rows x 128 k-cols, warp: 16 rows x 128 cols ----
        float s[16][4];
#pragma unroll
        for (int n = 0; n < 16; n++)
#pragma unroll
            for (int q = 0; q < 4; q++) s[n][q] = 0.f;

#pragma unroll
        for (int t = 0; t < 8; t++) {
            const int kb = t * 16;
            unsigned aoff = (unsigned)((wm * 16 + a_row_off) * FL_QROWB + (kb + a_kb_off) * 2);
            unsigned aq[4];
            ldsm_x4(sb + FL_QB + aoff, aq[0], aq[1], aq[2], aq[3]);
#pragma unroll
            for (int h = 0; h < 2; h++) {
                unsigned bk[4][4];
#pragma unroll
                for (int g4 = 0; g4 < 4; g4++) {
                    const int g = h * 4 + g4;
                    unsigned boff = (unsigned)((g * 16 + b_n_off) * FL_KROWB + (kb + b_k_off) * 2);
                    ldsm_x4(kB + boff, bk[g4][0], bk[g4][1], bk[g4][2], bk[g4][3]);
                }
#pragma unroll
                for (int g4 = 0; g4 < 4; g4++) {
                    const int g = h * 4 + g4;
                    mma_f16(s[2*g],   aq, bk[g4]);
                    mma_f16(s[2*g+1], aq, bk[g4] + 2);
                }
            }
        }

        // ---- causal mask (only diagonal tile: kt == qt) ----
        const int qr0 = qt * 128 + wm * 16 + (lane >> 2);
        const int qr1 = qr0 + 8;
        if (kt == qt) {
#pragma unroll
            for (int n = 0; n < 16; n++) {
                int c0 = kt * 128 + n * 8 + (lane & 3) * 2;
                if (c0     > qr0) s[n][0] = -1e30f;
                if (c0 + 1 > qr0) s[n][1] = -1e30f;
                if (c0     > qr1) s[n][2] = -1e30f;
                if (c0 + 1 > qr1) s[n][3] = -1e30f;
            }
        }

        // ---- online softmax (base-2 domain) ----
        float mx0 = -1e30f, mx1 = -1e30f;
#pragma unroll
        for (int n = 0; n < 16; n++) {
            mx0 = fmaxf(mx0, fmaxf(s[n][0], s[n][1]));
            mx1 = fmaxf(mx1, fmaxf(s[n][2], s[n][3]));
        }
        mx0 = fmaxf(mx0, __shfl_xor_sync(0xffffffffu, mx0, 1));
        mx0 = fmaxf(mx0, __shfl_xor_sync(0xffffffffu, mx0, 2));
        mx1 = fmaxf(mx1, __shfl_xor_sync(0xffffffffu, mx1, 1));
        mx1 = fmaxf(mx1, __shfl_xor_sync(0xffffffffu, mx1, 2));

        const float mn0 = fmaxf(m0, mx0);
        const float mn1 = fmaxf(m1, mx1);
        const float fac0 = ex2f(m0 - mn0);
        const float fac1 = ex2f(m1 - mn1);

        unsigned pA[8][4];
        float ls0 = 0.f, ls1 = 0.f;
#pragma unroll
        for (int t = 0; t < 8; t++) {
            float p00 = ex2f(s[2*t][0] - mn0),   p01 = ex2f(s[2*t][1] - mn0);
            float p02 = ex2f(s[2*t][2] - mn1),   p03 = ex2f(s[2*t][3] - mn1);
            float p10 = ex2f(s[2*t+1][0] - mn0), p11 = ex2f(s[2*t+1][1] - mn0);
            float p12 = ex2f(s[2*t+1][2] - mn1), p13 = ex2f(s[2*t+1][3] - mn1);
            ls0 += (p00 + p01) + (p10 + p11);
            ls1 += (p02 + p03) + (p12 + p13);
            pA[t][0] = cvt2_f16(p00, p01);
            pA[t][1] = cvt2_f16(p02, p03);
            pA[t][2] = cvt2_f16(p10, p11);
            pA[t][3] = cvt2_f16(p12, p13);
        }
        l0 = l0 * fac0 + ls0;
        l1 = l1 * fac1 + ls1;
        m0 = mn0; m1 = mn1;
#pragma unroll
        for (int n = 0; n < 16; n++) {
            o[n][0] *= fac0; o[n][1] *= fac0;
            o[n][2] *= fac1; o[n][3] *= fac1;
        }

        // ---- O += P @ V ----
#pragma unroll
        for (int t = 0; t < 8; t++) {
#pragma unroll
            for (int h = 0; h < 2; h++) {
                unsigned vr[4][4];
#pragma unroll
                for (int g4 = 0; g4 < 4; g4++) {
                    const int g = h * 4 + g4;
                    unsigned boff = (unsigned)((g * 16 + b_n_off) * FL_VROWB + (t * 16 + b_k_off) * 2);
                    ldsm_x4(vB + boff, vr[g4][0], vr[g4][1], vr[g4][2], vr[g4][3]);
                }
#pragma unroll
                for (int g4 = 0; g4 < 4; g4++) {
                    const int g = h * 4 + g4;
                    mma_f16(o[2*g],   pA[t], vr[g4]);
                    mma_f16(o[2*g+1], pA[t], vr[g4] + 2);
                }
            }
        }
    }

    // ---- epilogue ----
    l0 += __shfl_xor_sync(0xffffffffu, l0, 1);
    l0 += __shfl_xor_sync(0xffffffffu, l0, 2);
    l1 += __shfl_xor_sync(0xffffffffu, l1, 1);
    l1 += __shfl_xor_sync(0xffffffffu, l1, 2);

    const int r0 = wm * 16 + (lane >> 2);
    float* __restrict__ Og = g_O[sp] + (qrow0) * HEAD;
#pragma unroll
    for (int n = 0; n < 16; n++) {
        const int col = n * 8 + (lane & 3) * 2;
        *(float2*)&Og[(long)r0 * HEAD + col]       = make_float2(o[n][0], o[n][1]);
        *(float2*)&Og[(long)(r0 + 8) * HEAD + col] = make_float2(o[n][2], o[n][3]);
    }
    if ((lane & 3) == 0) {
        const long rowg = (long)b * SEQ + qt * 128 + r0;
        g_m[sp][rowg] = m0;     g_l[sp][rowg] = l0;
        g_m[sp][rowg + 8] = m1; g_l[sp][rowg + 8] = l1;
    }
}

// ---------------------------------------------------------------------------
// Combine active splits (base-2 weights), 8 elements/thread.
// ---------------------------------------------------------------------------
__global__ __launch_bounds__(256) void combine_kernel(float* __restrict__ out)
{
    const int id = blockIdx.x * 256 + threadIdx.x;
    const long base = (long)id * 8;
    const int row = (int)(base >> 7);
    const int qt = (row & 2047) >> 7;
    const int nkt = qt + 1;
    const int chunk = (nkt + NSPLIT - 1) / NSPLIT;
    const int ns = (nkt + chunk - 1) / chunk;

    float M = -1e30f;
    for (int s = 0; s < ns; s++) M = fmaxf(M, g_m[s][row]);

    float4 n0 = make_float4(0.f, 0.f, 0.f, 0.f);
    float4 n1 = make_float4(0.f, 0.f, 0.f, 0.f);
    float den = 0.f;
    for (int s = 0; s < ns; s++) {
        float w = ex2f(g_m[s][row] - M);
        float4 a = *(const float4*)&g_O[s][base];
        float4 c = *(const float4*)&g_O[s][base + 4];
        n0.x += w * a.x; n0.y += w * a.y; n0.z += w * a.z; n0.w += w * a.w;
        n1.x += w * c.x; n1.y += w * c.y; n1.z += w * c.z; n1.w += w * c.w;
        den += w * g_l[s][row];
    }
    float inv = 1.0f / den;
    *(float4*)&out[base]     = make_float4(n0.x*inv, n0.y*inv, n0.z*inv, n0.w*inv);
    *(float4*)&out[base + 4] = make_float4(n1.x*inv, n1.y*inv, n1.z*inv, n1.w*inv);
}

// ---------------------------------------------------------------------------
extern "C" void kernel_launch(void* const* d_in, const int* in_sizes, int n_in,
                              void* d_out, int out_size)
{
    const float* X  = (const float*)d_in[0];
    const float* WQ = (const float*)d_in[1];
    const float* WK = (const float*)d_in[2];
    const float* WV = (const float*)d_in[3];
    float* out = (float*)d_out;

    cudaFuncSetAttribute(proj_mma_kernel,
                         cudaFuncAttributeMaxDynamicSharedMemorySize, PJ_SMEM);
    cudaFuncSetAttribute(flash_kernel,
                         cudaFuncAttributeMaxDynamicSharedMemorySize, FL_SMEM);

    convert_all_kernel<<<(int)((XN + BN + VN) / 1024), 256>>>(X, WQ, WK, WV);
    proj_mma_kernel<<<dim3(64, 2), 256, PJ_SMEM>>>();
    flash_kernel<<<BATCH * 16 * NSPLIT, 256, FL_SMEM>>>();
    combine_kernel<<<(BATCH*SEQ*HEAD/8)/256, 256>>>(out);
}